// round 4
// baseline (speedup 1.0000x reference)
#include <cuda_runtime.h>
#include <cuda_bf16.h>
#include <math.h>
#include <stdint.h>

// Problem constants
#define B_ROWS   16384
#define DIM      2048
#define OUT_CL   1000
#define N_INNER  255
#define N_LEAF   256

#define BK      32
#define NCHUNK  (DIM / BK)

// ---------------- device scratch (no allocation allowed) ----------------
__device__ float  g_probs[(size_t)B_ROWS * 256];   // sigmoid(beta*(xW^T+b)), padded N=256
__device__ float  g_Q[(size_t)N_LEAF * OUT_CL];    // exp(log_softmax(leaf_params))
__device__ float  g_logQt[(size_t)OUT_CL * N_LEAF];// transposed log_softmax
__device__ float  g_leafSum[N_LEAF];               // sum over batch of leaf path probs
__device__ double g_lossSum;                       // sum over batch of dot(path, logQ[:,t])
__device__ int    g_t[B_ROWS];                     // target index per row
__device__ int    g_best[B_ROWS];                  // argmax leaf per row
__device__ float  g_Whi[(size_t)256 * DIM];        // tf32(W), row 255 = 0
__device__ float  g_Wlo[(size_t)256 * DIM];        // tf32(W - tf32(W))

// ---------------- helpers ----------------
__device__ __forceinline__ uint32_t smem_u32(const void* p) {
    uint32_t a;
    asm("{ .reg .u64 t; cvta.to.shared.u64 t, %1; cvt.u32.u64 %0, t; }" : "=r"(a) : "l"(p));
    return a;
}
__device__ __forceinline__ float tf32r(float x) {
    uint32_t u;
    asm("cvt.rna.tf32.f32 %0, %1;" : "=r"(u) : "f"(x));
    return __uint_as_float(u);
}
__device__ __forceinline__ void mma8(float* c, const uint32_t* a, const uint32_t* b) {
    asm volatile("mma.sync.aligned.m16n8k8.row.col.f32.tf32.tf32.f32 "
        "{%0,%1,%2,%3}, {%4,%5,%6,%7}, {%8,%9}, {%0,%1,%2,%3};"
        : "+f"(c[0]), "+f"(c[1]), "+f"(c[2]), "+f"(c[3])
        : "r"(a[0]), "r"(a[1]), "r"(a[2]), "r"(a[3]), "r"(b[0]), "r"(b[1]));
}
#define CP_ASYNC16(dst, src) asm volatile("cp.async.cg.shared.global [%0], [%1], 16;" :: "r"(dst), "l"(src))
#define CP_COMMIT()          asm volatile("cp.async.commit_group;")
#define CP_WAIT0()           asm volatile("cp.async.wait_group 0;" ::: "memory")

// ---------------- init ----------------
__global__ void init_kernel() {
    int t = threadIdx.x;
    if (t < N_LEAF) g_leafSum[t] = 0.0f;
    if (t == 0) g_lossSum = 0.0;
}

// ---------------- W split ----------------
__global__ void wsplit_kernel(const float* __restrict__ W) {
    int n = blockIdx.x;
    for (int k = threadIdx.x; k < DIM; k += 256) {
        float w = (n < N_INNER) ? W[(size_t)n * DIM + k] : 0.0f;
        float h = tf32r(w);
        float l = tf32r(w - h);
        g_Whi[(size_t)n * DIM + k] = h;
        g_Wlo[(size_t)n * DIM + k] = l;
    }
}

// ---------------- log_softmax of leaf_params ----------------
__global__ void softmax_kernel(const float* __restrict__ lp) {
    __shared__ float red[256];
    int r = blockIdx.x;
    int tid = threadIdx.x;
    const float* row = lp + (size_t)r * OUT_CL;

    float m = -INFINITY;
    for (int j = tid; j < OUT_CL; j += 256) m = fmaxf(m, row[j]);
    red[tid] = m; __syncthreads();
    for (int s = 128; s; s >>= 1) { if (tid < s) red[tid] = fmaxf(red[tid], red[tid + s]); __syncthreads(); }
    float rowmax = red[0];
    __syncthreads();

    float sum = 0.0f;
    for (int j = tid; j < OUT_CL; j += 256) sum += expf(row[j] - rowmax);
    red[tid] = sum; __syncthreads();
    for (int s = 128; s; s >>= 1) { if (tid < s) red[tid] += red[tid + s]; __syncthreads(); }
    float lse = rowmax + logf(red[0]);

    for (int j = tid; j < OUT_CL; j += 256) {
        float lq = row[j] - lse;
        g_Q[(size_t)r * OUT_CL + j] = expf(lq);
        g_logQt[(size_t)j * N_LEAF + r] = lq;
    }
}

// ---------------- target extraction ----------------
__global__ void target_kernel(const float* __restrict__ y) {
    int warp = threadIdx.x >> 5, lane = threadIdx.x & 31;
    int gw = blockIdx.x * (blockDim.x >> 5) + warp;
    int nw = gridDim.x * (blockDim.x >> 5);
    for (int b = gw; b < B_ROWS; b += nw) {
        const float* row = y + (size_t)b * OUT_CL;
        float bv = -INFINITY; int bi = 0;
        for (int j = lane; j < OUT_CL; j += 32) {
            float v = __ldg(row + j);
            if (v > bv) { bv = v; bi = j; }
        }
        for (int off = 16; off; off >>= 1) {
            float ov = __shfl_down_sync(0xffffffffu, bv, off);
            int   oi = __shfl_down_sync(0xffffffffu, bi, off);
            if (ov > bv || (ov == bv && oi < bi)) { bv = ov; bi = oi; }
        }
        if (lane == 0) g_t[b] = bi;
    }
}

// ---------------- 3xTF32 mma.sync GEMM: probs = sigmoid(beta*(x@W^T + b)) -----
// CTA 128x128, BK=32, 8 warps (4x2), warp tile 32x64.
// SMEM per buffer: A[2 split][128][32] + B[2 split][128][32] = 16384 floats.
// Double buffered: 32768 floats = 128 KB.
#define GEMM_SMEM (32768 * 4)

__device__ __forceinline__ int aOff(int buf, int split, int row, int col) {
    return buf * 16384 + split * 4096 + row * 32 + (col ^ ((row & 7) << 2));
}
__device__ __forceinline__ int bOff(int buf, int split, int row, int col) {
    return buf * 16384 + 8192 + split * 4096 + row * 32 + (col ^ ((row & 7) << 2));
}

__global__ __launch_bounds__(256, 1)
void gemm_mma_kernel(const float* __restrict__ X,
                     const float* __restrict__ bias, const float* __restrict__ beta) {
    extern __shared__ __align__(16) float smem[];
    const int tid  = threadIdx.x;
    const int lane = tid & 31, wid = tid >> 5;
    const int wm = wid & 3, wn = wid >> 2;
    const int gid = lane >> 2, tig = lane & 3;
    const int mBase = blockIdx.x * 128;
    const int nBase = blockIdx.y * 128;
    const uint32_t sbase = smem_u32(smem);

    const int frow = tid >> 1;            // 0..127
    const int fq   = (tid & 1) * 4;       // quad index base (0 or 4)

    float c[2][8][4];
    #pragma unroll
    for (int i = 0; i < 2; i++)
        #pragma unroll
        for (int j = 0; j < 8; j++)
            #pragma unroll
            for (int k = 0; k < 4; k++) c[i][j][k] = 0.0f;

    // ---- fill helpers ----
    auto issueB = [&](int chunk, int buf) {
        int k0 = chunk * BK;
        const float* srcH = g_Whi + (size_t)(nBase + frow) * DIM + k0;
        const float* srcL = g_Wlo + (size_t)(nBase + frow) * DIM + k0;
        #pragma unroll
        for (int j = 0; j < 4; j++) {
            int col = (fq + j) * 4;
            CP_ASYNC16(sbase + (uint32_t)bOff(buf, 0, frow, col) * 4, srcH + col);
            CP_ASYNC16(sbase + (uint32_t)bOff(buf, 1, frow, col) * 4, srcL + col);
        }
    };
    auto loadA = [&](int chunk, float4* av) {
        int k0 = chunk * BK;
        const float* src = X + (size_t)(mBase + frow) * DIM + k0;
        #pragma unroll
        for (int j = 0; j < 4; j++) av[j] = *(const float4*)(src + (fq + j) * 4);
    };
    auto storeA = [&](const float4* av, int buf) {
        #pragma unroll
        for (int j = 0; j < 4; j++) {
            float4 v = av[j];
            float h0 = tf32r(v.x), h1 = tf32r(v.y), h2 = tf32r(v.z), h3 = tf32r(v.w);
            float l0 = tf32r(v.x - h0), l1 = tf32r(v.y - h1), l2 = tf32r(v.z - h2), l3 = tf32r(v.w - h3);
            int col = (fq + j) * 4;
            *(float4*)(smem + aOff(buf, 0, frow, col)) = make_float4(h0, h1, h2, h3);
            *(float4*)(smem + aOff(buf, 1, frow, col)) = make_float4(l0, l1, l2, l3);
        }
    };

    // ---- prologue ----
    {
        issueB(0, 0); CP_COMMIT();
        float4 av[4];
        loadA(0, av);
        storeA(av, 0);
        CP_WAIT0();
        __syncthreads();
    }

    // ---- mainloop ----
    for (int ch = 0; ch < NCHUNK; ch++) {
        const int cur = ch & 1, nxt = cur ^ 1;
        float4 av[4];
        if (ch + 1 < NCHUNK) {
            loadA(ch + 1, av);
            issueB(ch + 1, nxt); CP_COMMIT();
        }

        #pragma unroll
        for (int kk = 0; kk < 4; kk++) {
            uint32_t a[2][2][4];
            #pragma unroll
            for (int s = 0; s < 2; s++)
                #pragma unroll
                for (int mt = 0; mt < 2; mt++) {
                    int r0 = wm * 32 + mt * 16 + gid;
                    int col = kk * 8 + tig;
                    a[s][mt][0] = __float_as_uint(smem[aOff(cur, s, r0,     col)]);
                    a[s][mt][1] = __float_as_uint(smem[aOff(cur, s, r0 + 8, col)]);
                    a[s][mt][2] = __float_as_uint(smem[aOff(cur, s, r0,     col + 4)]);
                    a[s][mt][3] = __float_as_uint(smem[aOff(cur, s, r0 + 8, col + 4)]);
                }
            uint32_t b[2][8][2];
            #pragma unroll
            for (int s = 0; s < 2; s++)
                #pragma unroll
                for (int nt = 0; nt < 8; nt++) {
                    int n = wn * 64 + nt * 8 + gid;
                    int col = kk * 8 + tig;
                    b[s][nt][0] = __float_as_uint(smem[bOff(cur, s, n, col)]);
                    b[s][nt][1] = __float_as_uint(smem[bOff(cur, s, n, col + 4)]);
                }
            #pragma unroll
            for (int mt = 0; mt < 2; mt++)
                #pragma unroll
                for (int nt = 0; nt < 8; nt++) {
                    mma8(c[mt][nt], a[0][mt], b[0][nt]);  // hi*hi
                    mma8(c[mt][nt], a[0][mt], b[1][nt]);  // hi*lo
                    mma8(c[mt][nt], a[1][mt], b[0][nt]);  // lo*hi
                }
        }

        if (ch + 1 < NCHUNK) {
            storeA(av, nxt);
            CP_WAIT0();
        }
        __syncthreads();
    }

    // ---- epilogue: sigmoid(beta*(acc+bias)) -> g_probs ----
    #pragma unroll
    for (int mt = 0; mt < 2; mt++) {
        int r = mBase + wm * 32 + mt * 16 + gid;
        #pragma unroll
        for (int nt = 0; nt < 8; nt++) {
            int n0 = nBase + wn * 64 + nt * 8 + 2 * tig;
            float be0 = (n0     < N_INNER) ? __ldg(beta + n0)     : 0.0f;
            float be1 = (n0 + 1 < N_INNER) ? __ldg(beta + n0 + 1) : 0.0f;
            float bi0 = (n0     < N_INNER) ? __ldg(bias + n0)     : 0.0f;
            float bi1 = (n0 + 1 < N_INNER) ? __ldg(bias + n0 + 1) : 0.0f;
            float2 o0, o1;
            {
                float z = be0 * (c[mt][nt][0] + bi0);
                o0.x = (n0 < N_INNER) ? 1.0f / (1.0f + expf(-z)) : 0.0f;
            }
            {
                float z = be1 * (c[mt][nt][1] + bi1);
                o0.y = (n0 + 1 < N_INNER) ? 1.0f / (1.0f + expf(-z)) : 0.0f;
            }
            {
                float z = be0 * (c[mt][nt][2] + bi0);
                o1.x = (n0 < N_INNER) ? 1.0f / (1.0f + expf(-z)) : 0.0f;
            }
            {
                float z = be1 * (c[mt][nt][3] + bi1);
                o1.y = (n0 + 1 < N_INNER) ? 1.0f / (1.0f + expf(-z)) : 0.0f;
            }
            *(float2*)(g_probs + (size_t)r * 256 + n0)       = o0;
            *(float2*)(g_probs + (size_t)(r + 8) * 256 + n0) = o1;
        }
    }
}

// ---------------- tree expansion ----------------
__global__ __launch_bounds__(256)
void path_kernel() {
    __shared__ float sp[8][256];
    __shared__ float red[256];
    const int warp = threadIdx.x >> 5, lane = threadIdx.x & 31;
    const int gw = blockIdx.x * 8 + warp;
    const int nw = gridDim.x * 8;
    const int base = lane * 8;

    float lacc[8];
    #pragma unroll
    for (int k = 0; k < 8; k++) lacc[k] = 0.0f;
    float dacc = 0.0f;

    for (int b = gw; b < B_ROWS; b += nw) {
        const float* pr = g_probs + (size_t)b * 256;
        for (int i = lane; i < 256; i += 32) sp[warp][i] = pr[i];
        __syncwarp();

        float pre = 1.0f;
        #pragma unroll
        for (int d = 1; d <= 5; d++) {
            int g = (1 << (d - 1)) - 1 + (base >> (9 - d));
            int bit = (base >> (8 - d)) & 1;
            float pv = sp[warp][g];
            pre *= bit ? pv : (1.0f - pv);
        }
        float leaf[8];
        #pragma unroll
        for (int k = 0; k < 8; k++) {
            int l = base + k;
            float f = pre;
            #pragma unroll
            for (int d = 6; d <= 8; d++) {
                int g = (1 << (d - 1)) - 1 + (l >> (9 - d));
                int bit = (l >> (8 - d)) & 1;
                float pv = sp[warp][g];
                f *= bit ? pv : (1.0f - pv);
            }
            leaf[k] = f;
            lacc[k] += f;
        }

        int t = g_t[b];
        const float* lq = g_logQt + (size_t)t * 256 + base;
        float dl = 0.0f;
        #pragma unroll
        for (int k = 0; k < 8; k++) dl += leaf[k] * lq[k];
        dacc += dl;

        float bv = leaf[0]; int bi = base;
        #pragma unroll
        for (int k = 1; k < 8; k++) if (leaf[k] > bv) { bv = leaf[k]; bi = base + k; }
        for (int off = 16; off; off >>= 1) {
            float ov = __shfl_down_sync(0xffffffffu, bv, off);
            int   oi = __shfl_down_sync(0xffffffffu, bi, off);
            if (ov > bv || (ov == bv && oi < bi)) { bv = ov; bi = oi; }
        }
        if (lane == 0) g_best[b] = bi;
        __syncwarp();
    }

    #pragma unroll
    for (int k = 0; k < 8; k++) atomicAdd(&g_leafSum[base + k], lacc[k]);

    red[threadIdx.x] = dacc;
    __syncthreads();
    for (int s = 128; s; s >>= 1) { if (threadIdx.x < s) red[threadIdx.x] += red[threadIdx.x + s]; __syncthreads(); }
    if (threadIdx.x == 0) atomicAdd(&g_lossSum, (double)red[0]);
}

// ---------------- finalize ----------------
__global__ void final_kernel(float* __restrict__ out, int writeLoss) {
    if (threadIdx.x != 0 || blockIdx.x != 0) return;
    float S[255];
    for (int j = 0; j < 128; j++) S[127 + j] = g_leafSum[2 * j] + g_leafSum[2 * j + 1];
    for (int g = 126; g >= 0; g--) S[g] = S[2 * g + 1] + S[2 * g + 2];

    float C = 0.0f;
    int idx = 0;
    for (int d = 1; d <= 7; d++) {
        int n = 1 << (d - 1);
        float lm = 0.1f * exp2f((float)(-d)) * 0.5f;
        for (int j = 0; j < n; j++) {
            int g = idx + j;
            float denom = S[g];
            if (denom == 0.0f) denom = 1e-6f;
            float a = S[2 * g + 2] / denom;
            a = fminf(fmaxf(a, 1e-6f), 1.0f - 1e-6f);
            C -= lm * (logf(a) + log1pf(-a));
        }
        idx += n;
    }
    double lt = g_lossSum / (double)B_ROWS;
    if (writeLoss) out[0] = (float)(-lt + (double)C);
}

// ---------------- output gather ----------------
__global__ void gather_kernel(float* __restrict__ out) {
    for (int b = blockIdx.x; b < B_ROWS; b += gridDim.x) {
        const float* q = g_Q + (size_t)g_best[b] * OUT_CL;
        float* o = out + (size_t)b * OUT_CL;
        for (int j = threadIdx.x; j < OUT_CL; j += blockDim.x) o[j] = q[j];
    }
}

extern "C" void kernel_launch(void* const* d_in, const int* in_sizes, int n_in,
                              void* d_out, int out_size) {
    const float* x    = (const float*)d_in[0];
    const float* y    = (const float*)d_in[1];
    const float* W    = (const float*)d_in[2];
    const float* bias = (const float*)d_in[3];
    const float* beta = (const float*)d_in[4];
    const float* lp   = (const float*)d_in[5];
    float* out = (float*)d_out;

    int hasLoss = (out_size >= B_ROWS * OUT_CL + 1) ? 1 : 0;
    float* outRows = out + hasLoss;

    static int smemSet = 0;
    if (!smemSet) {
        cudaFuncSetAttribute(gemm_mma_kernel, cudaFuncAttributeMaxDynamicSharedMemorySize, GEMM_SMEM);
        smemSet = 1;
    }

    init_kernel<<<1, 256>>>();
    wsplit_kernel<<<256, 256>>>(W);
    softmax_kernel<<<N_LEAF, 256>>>(lp);
    target_kernel<<<2048, 256>>>(y);
    gemm_mma_kernel<<<dim3(128, 2), 256, GEMM_SMEM>>>(x, bias, beta);
    path_kernel<<<512, 256>>>();
    final_kernel<<<1, 32>>>(out, hasLoss);
    gather_kernel<<<2048, 256>>>(outRows);
}

// round 6
// speedup vs baseline: 1.3439x; 1.3439x over previous
#include <cuda_runtime.h>
#include <cuda_fp16.h>
#include <cuda_bf16.h>
#include <math.h>
#include <stdint.h>

// Problem constants
#define B_ROWS   16384
#define DIM      2048
#define OUT_CL   1000
#define N_INNER  255
#define N_LEAF   256

#define BK      32
#define NCHUNK  (DIM / BK)
#define SCALE     1024.0f
#define SCALE_INV (1.0f / (1024.0f * 1024.0f))

// ---------------- device scratch ----------------
__device__ float  g_probs[(size_t)B_ROWS * 256];
__device__ float  g_Q[(size_t)N_LEAF * OUT_CL];
__device__ float  g_logQt[(size_t)OUT_CL * N_LEAF];
__device__ float  g_leafSum[N_LEAF];
__device__ double g_lossSum;
__device__ int    g_t[B_ROWS];
__device__ int    g_best[B_ROWS];
// W split to fp16 hi/lo, scaled by 1024: [n][chunk][hi 0..31 | lo 32..63]
__device__ __half g_Wsp[(size_t)256 * DIM * 2];

// ---------------- helpers ----------------
__device__ __forceinline__ uint32_t smem_u32(const void* p) {
    uint32_t a;
    asm("{ .reg .u64 t; cvta.to.shared.u64 t, %1; cvt.u32.u64 %0, t; }" : "=r"(a) : "l"(p));
    return a;
}
__device__ __forceinline__ void mma16(float* c, const uint32_t* a, const uint32_t* b) {
    asm volatile("mma.sync.aligned.m16n8k16.row.col.f32.f16.f16.f32 "
        "{%0,%1,%2,%3}, {%4,%5,%6,%7}, {%8,%9}, {%0,%1,%2,%3};"
        : "+f"(c[0]), "+f"(c[1]), "+f"(c[2]), "+f"(c[3])
        : "r"(a[0]), "r"(a[1]), "r"(a[2]), "r"(a[3]), "r"(b[0]), "r"(b[1]));
}
#define LDSM4(r, a) asm volatile("ldmatrix.sync.aligned.m8n8.x4.shared.b16 {%0,%1,%2,%3}, [%4];" \
    : "=r"((r)[0]), "=r"((r)[1]), "=r"((r)[2]), "=r"((r)[3]) : "r"(a))
#define CP_ASYNC16(dst, src) asm volatile("cp.async.cg.shared.global [%0], [%1], 16;" :: "r"(dst), "l"(src))
#define CP_COMMIT()          asm volatile("cp.async.commit_group;")
#define CP_WAIT0()           asm volatile("cp.async.wait_group 0;" ::: "memory")

// ---------------- init ----------------
__global__ void init_kernel() {
    int t = threadIdx.x;
    if (t < N_LEAF) g_leafSum[t] = 0.0f;
    if (t == 0) g_lossSum = 0.0;
}

// ---------------- W split to fp16 hi/lo (scaled by 1024) ----------------
__global__ void wsplit_kernel(const float* __restrict__ W) {
    int n = blockIdx.x;
    for (int k = threadIdx.x; k < DIM; k += 256) {
        float w = (n < N_INNER) ? W[(size_t)n * DIM + k] * SCALE : 0.0f;
        __half h = __float2half_rn(w);
        __half l = __float2half_rn(w - __half2float(h));
        int ch = k >> 5, s = k & 31;
        size_t base = (size_t)n * (DIM * 2) + ch * 64;
        g_Wsp[base + s]      = h;
        g_Wsp[base + 32 + s] = l;
    }
}

// ---------------- log_softmax of leaf_params ----------------
__global__ void softmax_kernel(const float* __restrict__ lp) {
    __shared__ float red[256];
    int r = blockIdx.x;
    int tid = threadIdx.x;
    const float* row = lp + (size_t)r * OUT_CL;

    float m = -INFINITY;
    for (int j = tid; j < OUT_CL; j += 256) m = fmaxf(m, row[j]);
    red[tid] = m; __syncthreads();
    for (int s = 128; s; s >>= 1) { if (tid < s) red[tid] = fmaxf(red[tid], red[tid + s]); __syncthreads(); }
    float rowmax = red[0];
    __syncthreads();

    float sum = 0.0f;
    for (int j = tid; j < OUT_CL; j += 256) sum += expf(row[j] - rowmax);
    red[tid] = sum; __syncthreads();
    for (int s = 128; s; s >>= 1) { if (tid < s) red[tid] += red[tid + s]; __syncthreads(); }
    float lse = rowmax + logf(red[0]);

    for (int j = tid; j < OUT_CL; j += 256) {
        float lq = row[j] - lse;
        g_Q[(size_t)r * OUT_CL + j] = expf(lq);
        g_logQt[(size_t)j * N_LEAF + r] = lq;
    }
}

// ---------------- target extraction (one-hot, early exit) ----------------
__global__ void target_kernel(const float* __restrict__ y) {
    int warp = threadIdx.x >> 5, lane = threadIdx.x & 31;
    int gw = blockIdx.x * (blockDim.x >> 5) + warp;
    int nw = gridDim.x * (blockDim.x >> 5);
    for (int b = gw; b < B_ROWS; b += nw) {
        const float* row = y + (size_t)b * OUT_CL;
        int found = 0;
        for (int jb = 0; jb < 1024; jb += 32) {
            int j = jb + lane;
            float v = (j < OUT_CL) ? __ldg(row + j) : 0.0f;
            unsigned msk = __ballot_sync(0xffffffffu, v > 0.5f);
            if (msk) {
                int src = __ffs(msk) - 1;
                found = jb + src;
                break;
            }
        }
        if (lane == 0) g_t[b] = found;
    }
}

// ---------------- fp16 3-product mma GEMM: probs = sigmoid(beta*(x@W^T + b)) --
// CTA: M=128, N=128 (blockIdx.y in {0,1}), 512 threads = 16 warps (4x4),
// warp tile 32x32. K chunks of 32, fp16 hi/lo -> k'=64 per chunk.
// SMEM: [A0 16K][B0 16K][A1 16K][B1 16K] = 64 KB. Rows = 64 fp16 = 128B = 8 units.
#define GEMM_SMEM 65536

__global__ __launch_bounds__(512, 1)
void gemm_mma_kernel(const float* __restrict__ X,
                     const float* __restrict__ bias, const float* __restrict__ beta) {
    extern __shared__ __align__(16) char smemc[];
    const int tid  = threadIdx.x;
    const int lane = tid & 31, wid = tid >> 5;
    const int warpM = wid & 3, warpN = wid >> 2;
    const int mBase = blockIdx.x * 128;
    const int nBase = blockIdx.y * 128;
    const uint32_t sb = smem_u32(smemc);

    // ldmatrix per-lane address components
    const int aRow = warpM * 32 + (lane & 15);          // + mt*16
    const int aU   = lane >> 4;                          // +0/+1 unit
    const int bRow = warpN * 32 + (lane & 7) + ((lane >> 4) << 3);  // + ntp*16
    const int bU   = (lane >> 3) & 1;

    // fill roles
    const int frow = tid >> 2;           // 0..127
    const int foct = tid & 3;            // fp32 octet / cp.async pair

    float c[2][4][4];
    #pragma unroll
    for (int i = 0; i < 2; i++)
        #pragma unroll
        for (int j = 0; j < 4; j++)
            #pragma unroll
            for (int k = 0; k < 4; k++) c[i][j][k] = 0.0f;

    auto aAddr = [&](int buf, int mt, int u0) -> uint32_t {
        int row = aRow + mt * 16;
        return sb + buf * 32768 + row * 128 + (((u0 + aU) ^ (row & 7)) << 4);
    };
    auto bAddr = [&](int buf, int ntp, int u0) -> uint32_t {
        int row = bRow + ntp * 16;
        return sb + 16384 + buf * 32768 + row * 128 + (((u0 + bU) ^ (row & 7)) << 4);
    };

    auto issueB = [&](int ch, int buf) {
        const __half* src = g_Wsp + (size_t)(nBase + frow) * (DIM * 2) + ch * 64;
        uint32_t dstRow = sb + 16384 + buf * 32768 + frow * 128;
        int x = frow & 7;
        int u0 = foct * 2;
        CP_ASYNC16(dstRow + ((u0 ^ x) << 4),       src + u0 * 8);
        CP_ASYNC16(dstRow + (((u0 + 1) ^ x) << 4), src + u0 * 8 + 8);
    };
    auto loadA = [&](int ch, float4* v) {
        const float* src = X + (size_t)(mBase + frow) * DIM + ch * BK + foct * 8;
        v[0] = *(const float4*)(src);
        v[1] = *(const float4*)(src + 4);
    };
    auto storeA = [&](const float4* v, int buf) {
        __half h[8], l[8];
        const float* f = (const float*)v;
        #pragma unroll
        for (int i = 0; i < 8; i++) {
            float s = f[i] * SCALE;
            h[i] = __float2half_rn(s);
            l[i] = __float2half_rn(s - __half2float(h[i]));
        }
        uint32_t rowAddr = sb + buf * 32768 + frow * 128;
        int x = frow & 7;
        uint32_t aH = rowAddr + ((foct ^ x) << 4);
        uint32_t aL = rowAddr + (((4 + foct) ^ x) << 4);
        uint4 ph = *(const uint4*)h;
        uint4 pl = *(const uint4*)l;
        asm volatile("st.shared.v4.b32 [%0], {%1,%2,%3,%4};" :: "r"(aH), "r"(ph.x), "r"(ph.y), "r"(ph.z), "r"(ph.w));
        asm volatile("st.shared.v4.b32 [%0], {%1,%2,%3,%4};" :: "r"(aL), "r"(pl.x), "r"(pl.y), "r"(pl.z), "r"(pl.w));
    };

    // prologue
    {
        issueB(0, 0); CP_COMMIT();
        float4 v[2];
        loadA(0, v);
        storeA(v, 0);
        CP_WAIT0();
        __syncthreads();
    }

    for (int ch = 0; ch < NCHUNK; ch++) {
        const int cur = ch & 1, nxt = cur ^ 1;
        float4 v[2];
        if (ch + 1 < NCHUNK) {
            loadA(ch + 1, v);
            issueB(ch + 1, nxt); CP_COMMIT();
        }

        #pragma unroll
        for (int kst = 0; kst < 2; kst++) {
            const int uH = 2 * kst, uL = 4 + 2 * kst;
            uint32_t aH[2][4], aL[2][4], bH[2][4], bL[2][4];
            LDSM4(aH[0], aAddr(cur, 0, uH)); LDSM4(aH[1], aAddr(cur, 1, uH));
            LDSM4(aL[0], aAddr(cur, 0, uL)); LDSM4(aL[1], aAddr(cur, 1, uL));
            LDSM4(bH[0], bAddr(cur, 0, uH)); LDSM4(bH[1], bAddr(cur, 1, uH));
            LDSM4(bL[0], bAddr(cur, 0, uL)); LDSM4(bL[1], bAddr(cur, 1, uL));
            #pragma unroll
            for (int mt = 0; mt < 2; mt++)
                #pragma unroll
                for (int ntp = 0; ntp < 2; ntp++) {
                    mma16(c[mt][ntp * 2],     aH[mt], bH[ntp]);      // hi*HI
                    mma16(c[mt][ntp * 2 + 1], aH[mt], bH[ntp] + 2);
                    mma16(c[mt][ntp * 2],     aH[mt], bL[ntp]);      // hi*LO
                    mma16(c[mt][ntp * 2 + 1], aH[mt], bL[ntp] + 2);
                    mma16(c[mt][ntp * 2],     aL[mt], bH[ntp]);      // lo*HI
                    mma16(c[mt][ntp * 2 + 1], aL[mt], bH[ntp] + 2);
                }
        }

        if (ch + 1 < NCHUNK) {
            storeA(v, nxt);
            CP_WAIT0();
        }
        __syncthreads();
    }

    // epilogue
    const int group = lane >> 2, tig = lane & 3;
    #pragma unroll
    for (int mt = 0; mt < 2; mt++) {
        int r0 = mBase + warpM * 32 + mt * 16 + group;
        #pragma unroll
        for (int nt = 0; nt < 4; nt++) {
            int n0 = nBase + warpN * 32 + nt * 8 + tig * 2;
            float be0 = (n0     < N_INNER) ? __ldg(beta + n0)     : 0.0f;
            float be1 = (n0 + 1 < N_INNER) ? __ldg(beta + n0 + 1) : 0.0f;
            float bi0 = (n0     < N_INNER) ? __ldg(bias + n0)     : 0.0f;
            float bi1 = (n0 + 1 < N_INNER) ? __ldg(bias + n0 + 1) : 0.0f;
            float2 o0, o1;
            {
                float z = be0 * (c[mt][nt][0] * SCALE_INV + bi0);
                o0.x = (n0 < N_INNER) ? 1.0f / (1.0f + expf(-z)) : 0.0f;
            }
            {
                float z = be1 * (c[mt][nt][1] * SCALE_INV + bi1);
                o0.y = (n0 + 1 < N_INNER) ? 1.0f / (1.0f + expf(-z)) : 0.0f;
            }
            {
                float z = be0 * (c[mt][nt][2] * SCALE_INV + bi0);
                o1.x = (n0 < N_INNER) ? 1.0f / (1.0f + expf(-z)) : 0.0f;
            }
            {
                float z = be1 * (c[mt][nt][3] * SCALE_INV + bi1);
                o1.y = (n0 + 1 < N_INNER) ? 1.0f / (1.0f + expf(-z)) : 0.0f;
            }
            *(float2*)(g_probs + (size_t)r0 * 256 + n0)       = o0;
            *(float2*)(g_probs + (size_t)(r0 + 8) * 256 + n0) = o1;
        }
    }
}

// ---------------- tree expansion ----------------
__global__ __launch_bounds__(256)
void path_kernel() {
    __shared__ float sp[8][256];
    __shared__ float red[256];
    const int warp = threadIdx.x >> 5, lane = threadIdx.x & 31;
    const int gw = blockIdx.x * 8 + warp;
    const int nw = gridDim.x * 8;
    const int base = lane * 8;

    float lacc[8];
    #pragma unroll
    for (int k = 0; k < 8; k++) lacc[k] = 0.0f;
    float dacc = 0.0f;

    for (int b = gw; b < B_ROWS; b += nw) {
        const float* pr = g_probs + (size_t)b * 256;
        for (int i = lane; i < 256; i += 32) sp[warp][i] = pr[i];
        __syncwarp();

        float pre = 1.0f;
        #pragma unroll
        for (int d = 1; d <= 5; d++) {
            int g = (1 << (d - 1)) - 1 + (base >> (9 - d));
            int bit = (base >> (8 - d)) & 1;
            float pv = sp[warp][g];
            pre *= bit ? pv : (1.0f - pv);
        }
        float leaf[8];
        #pragma unroll
        for (int k = 0; k < 8; k++) {
            int l = base + k;
            float f = pre;
            #pragma unroll
            for (int d = 6; d <= 8; d++) {
                int g = (1 << (d - 1)) - 1 + (l >> (9 - d));
                int bit = (l >> (8 - d)) & 1;
                float pv = sp[warp][g];
                f *= bit ? pv : (1.0f - pv);
            }
            leaf[k] = f;
            lacc[k] += f;
        }

        int t = g_t[b];
        const float* lq = g_logQt + (size_t)t * 256 + base;
        float dl = 0.0f;
        #pragma unroll
        for (int k = 0; k < 8; k++) dl += leaf[k] * lq[k];
        dacc += dl;

        float bv = leaf[0]; int bi = base;
        #pragma unroll
        for (int k = 1; k < 8; k++) if (leaf[k] > bv) { bv = leaf[k]; bi = base + k; }
        for (int off = 16; off; off >>= 1) {
            float ov = __shfl_down_sync(0xffffffffu, bv, off);
            int   oi = __shfl_down_sync(0xffffffffu, bi, off);
            if (ov > bv || (ov == bv && oi < bi)) { bv = ov; bi = oi; }
        }
        if (lane == 0) g_best[b] = bi;
        __syncwarp();
    }

    #pragma unroll
    for (int k = 0; k < 8; k++) atomicAdd(&g_leafSum[base + k], lacc[k]);

    red[threadIdx.x] = dacc;
    __syncthreads();
    for (int s = 128; s; s >>= 1) { if (threadIdx.x < s) red[threadIdx.x] += red[threadIdx.x + s]; __syncthreads(); }
    if (threadIdx.x == 0) atomicAdd(&g_lossSum, (double)red[0]);
}

// ---------------- finalize ----------------
__global__ void final_kernel(float* __restrict__ out, int writeLoss) {
    if (threadIdx.x != 0 || blockIdx.x != 0) return;
    float S[255];
    for (int j = 0; j < 128; j++) S[127 + j] = g_leafSum[2 * j] + g_leafSum[2 * j + 1];
    for (int g = 126; g >= 0; g--) S[g] = S[2 * g + 1] + S[2 * g + 2];

    float C = 0.0f;
    int idx = 0;
    for (int d = 1; d <= 7; d++) {
        int n = 1 << (d - 1);
        float lm = 0.1f * exp2f((float)(-d)) * 0.5f;
        for (int j = 0; j < n; j++) {
            int g = idx + j;
            float denom = S[g];
            if (denom == 0.0f) denom = 1e-6f;
            float a = S[2 * g + 2] / denom;
            a = fminf(fmaxf(a, 1e-6f), 1.0f - 1e-6f);
            C -= lm * (logf(a) + log1pf(-a));
        }
        idx += n;
    }
    double lt = g_lossSum / (double)B_ROWS;
    if (writeLoss) out[0] = (float)(-lt + (double)C);
}

// ---------------- output gather ----------------
__global__ void gather_kernel(float* __restrict__ out) {
    for (int b = blockIdx.x; b < B_ROWS; b += gridDim.x) {
        const float* q = g_Q + (size_t)g_best[b] * OUT_CL;
        float* o = out + (size_t)b * OUT_CL;
        for (int j = threadIdx.x; j < OUT_CL; j += blockDim.x) o[j] = q[j];
    }
}

extern "C" void kernel_launch(void* const* d_in, const int* in_sizes, int n_in,
                              void* d_out, int out_size) {
    const float* x    = (const float*)d_in[0];
    const float* y    = (const float*)d_in[1];
    const float* W    = (const float*)d_in[2];
    const float* bias = (const float*)d_in[3];
    const float* beta = (const float*)d_in[4];
    const float* lp   = (const float*)d_in[5];
    float* out = (float*)d_out;

    int hasLoss = (out_size >= B_ROWS * OUT_CL + 1) ? 1 : 0;
    float* outRows = out + hasLoss;

    static int smemSet = 0;
    if (!smemSet) {
        cudaFuncSetAttribute(gemm_mma_kernel, cudaFuncAttributeMaxDynamicSharedMemorySize, GEMM_SMEM);
        smemSet = 1;
    }

    init_kernel<<<1, 256>>>();
    wsplit_kernel<<<256, 256>>>(W);
    softmax_kernel<<<N_LEAF, 256>>>(lp);
    gemm_mma_kernel<<<dim3(128, 2), 512, GEMM_SMEM>>>(x, bias, beta);  // slot 4: profiled
    target_kernel<<<2048, 256>>>(y);
    path_kernel<<<512, 256>>>();
    final_kernel<<<1, 32>>>(out, hasLoss);
    gather_kernel<<<2048, 256>>>(outRows);
}

// round 7
// speedup vs baseline: 2.8988x; 2.1569x over previous
#include <cuda_runtime.h>
#include <cuda_fp16.h>
#include <cuda_bf16.h>
#include <math.h>
#include <stdint.h>

// Problem constants
#define B_ROWS   16384
#define DIM      2048
#define OUT_CL   1000
#define N_INNER  255
#define N_LEAF   256

#define BK      32
#define NCHUNK  (DIM / BK)
#define SCALE     1024.0f
#define SCALE_INV (1.0f / (1024.0f * 1024.0f))

// ---------------- device scratch ----------------
__device__ float  g_probs[(size_t)B_ROWS * 256];
__device__ float  g_Q[(size_t)N_LEAF * OUT_CL];
__device__ float  g_logQt[(size_t)OUT_CL * N_LEAF];
__device__ float  g_leafSum[N_LEAF];
__device__ double g_lossSum;
__device__ int    g_t[B_ROWS];
// W split to fp16 hi/lo, scaled by 1024: [n][chunk][hi 0..31 | lo 32..63]
__device__ __half g_Wsp[(size_t)256 * DIM * 2];

// ---------------- helpers ----------------
__device__ __forceinline__ uint32_t smem_u32(const void* p) {
    uint32_t a;
    asm("{ .reg .u64 t; cvta.to.shared.u64 t, %1; cvt.u32.u64 %0, t; }" : "=r"(a) : "l"(p));
    return a;
}
__device__ __forceinline__ void mma16(float* c, const uint32_t* a, const uint32_t* b) {
    asm volatile("mma.sync.aligned.m16n8k16.row.col.f32.f16.f16.f32 "
        "{%0,%1,%2,%3}, {%4,%5,%6,%7}, {%8,%9}, {%0,%1,%2,%3};"
        : "+f"(c[0]), "+f"(c[1]), "+f"(c[2]), "+f"(c[3])
        : "r"(a[0]), "r"(a[1]), "r"(a[2]), "r"(a[3]), "r"(b[0]), "r"(b[1]));
}
#define LDSM4(r, a) asm volatile("ldmatrix.sync.aligned.m8n8.x4.shared.b16 {%0,%1,%2,%3}, [%4];" \
    : "=r"((r)[0]), "=r"((r)[1]), "=r"((r)[2]), "=r"((r)[3]) : "r"(a))
#define CP_ASYNC16(dst, src) asm volatile("cp.async.cg.shared.global [%0], [%1], 16;" :: "r"(dst), "l"(src))
#define CP_COMMIT()          asm volatile("cp.async.commit_group;")
#define CP_WAIT0()           asm volatile("cp.async.wait_group 0;" ::: "memory")

// ---------------- init ----------------
__global__ void init_kernel() {
    int t = threadIdx.x;
    if (t < N_LEAF) g_leafSum[t] = 0.0f;
    if (t == 0) g_lossSum = 0.0;
}

// ---------------- W split to fp16 hi/lo (scaled by 1024) ----------------
__global__ void wsplit_kernel(const float* __restrict__ W) {
    int n = blockIdx.x;
    for (int k = threadIdx.x; k < DIM; k += 256) {
        float w = (n < N_INNER) ? W[(size_t)n * DIM + k] * SCALE : 0.0f;
        __half h = __float2half_rn(w);
        __half l = __float2half_rn(w - __half2float(h));
        int ch = k >> 5, s = k & 31;
        size_t base = (size_t)n * (DIM * 2) + ch * 64;
        g_Wsp[base + s]      = h;
        g_Wsp[base + 32 + s] = l;
    }
}

// ---------------- log_softmax of leaf_params ----------------
__global__ void softmax_kernel(const float* __restrict__ lp) {
    __shared__ float red[256];
    int r = blockIdx.x;
    int tid = threadIdx.x;
    const float* row = lp + (size_t)r * OUT_CL;

    float m = -INFINITY;
    for (int j = tid; j < OUT_CL; j += 256) m = fmaxf(m, row[j]);
    red[tid] = m; __syncthreads();
    for (int s = 128; s; s >>= 1) { if (tid < s) red[tid] = fmaxf(red[tid], red[tid + s]); __syncthreads(); }
    float rowmax = red[0];
    __syncthreads();

    float sum = 0.0f;
    for (int j = tid; j < OUT_CL; j += 256) sum += expf(row[j] - rowmax);
    red[tid] = sum; __syncthreads();
    for (int s = 128; s; s >>= 1) { if (tid < s) red[tid] += red[tid + s]; __syncthreads(); }
    float lse = rowmax + logf(red[0]);

    for (int j = tid; j < OUT_CL; j += 256) {
        float lq = row[j] - lse;
        g_Q[(size_t)r * OUT_CL + j] = expf(lq);
        g_logQt[(size_t)j * N_LEAF + r] = lq;
    }
}

// ---------------- target extraction (one-hot, early exit) ----------------
__global__ void target_kernel(const float* __restrict__ y) {
    int warp = threadIdx.x >> 5, lane = threadIdx.x & 31;
    int gw = blockIdx.x * (blockDim.x >> 5) + warp;
    int nw = gridDim.x * (blockDim.x >> 5);
    for (int b = gw; b < B_ROWS; b += nw) {
        const float* row = y + (size_t)b * OUT_CL;
        int found = 0;
        for (int jb = 0; jb < 1024; jb += 32) {
            int j = jb + lane;
            float v = (j < OUT_CL) ? __ldg(row + j) : 0.0f;
            unsigned msk = __ballot_sync(0xffffffffu, v > 0.5f);
            if (msk) {
                int src = __ffs(msk) - 1;
                found = jb + src;
                break;
            }
        }
        if (lane == 0) g_t[b] = found;
    }
}

// ---------------- fp16 3-product mma GEMM ----------------
// grid (2,128): x = N-half, y = M-block (adjacent CTAs share X rows in L2)
#define GEMM_SMEM 65536

__global__ __launch_bounds__(512, 1)
void gemm_mma_kernel(const float* __restrict__ X,
                     const float* __restrict__ bias, const float* __restrict__ beta) {
    extern __shared__ __align__(16) char smemc[];
    const int tid  = threadIdx.x;
    const int lane = tid & 31, wid = tid >> 5;
    const int warpM = wid & 3, warpN = wid >> 2;
    const int mBase = blockIdx.y * 128;
    const int nBase = blockIdx.x * 128;
    const uint32_t sb = smem_u32(smemc);

    const int aRow = warpM * 32 + (lane & 15);
    const int aU   = lane >> 4;
    const int bRow = warpN * 32 + (lane & 7) + ((lane >> 4) << 3);
    const int bU   = (lane >> 3) & 1;

    const int frow = tid >> 2;
    const int foct = tid & 3;

    float c[2][4][4];
    #pragma unroll
    for (int i = 0; i < 2; i++)
        #pragma unroll
        for (int j = 0; j < 4; j++)
            #pragma unroll
            for (int k = 0; k < 4; k++) c[i][j][k] = 0.0f;

    auto aAddr = [&](int buf, int mt, int u0) -> uint32_t {
        int row = aRow + mt * 16;
        return sb + buf * 32768 + row * 128 + (((u0 + aU) ^ (row & 7)) << 4);
    };
    auto bAddr = [&](int buf, int ntp, int u0) -> uint32_t {
        int row = bRow + ntp * 16;
        return sb + 16384 + buf * 32768 + row * 128 + (((u0 + bU) ^ (row & 7)) << 4);
    };

    auto issueB = [&](int ch, int buf) {
        const __half* src = g_Wsp + (size_t)(nBase + frow) * (DIM * 2) + ch * 64;
        uint32_t dstRow = sb + 16384 + buf * 32768 + frow * 128;
        int x = frow & 7;
        int u0 = foct * 2;
        CP_ASYNC16(dstRow + ((u0 ^ x) << 4),       src + u0 * 8);
        CP_ASYNC16(dstRow + (((u0 + 1) ^ x) << 4), src + u0 * 8 + 8);
    };
    auto loadA = [&](int ch, float4* v) {
        const float* src = X + (size_t)(mBase + frow) * DIM + ch * BK + foct * 8;
        v[0] = *(const float4*)(src);
        v[1] = *(const float4*)(src + 4);
    };
    auto storeA = [&](const float4* v, int buf) {
        __half h[8], l[8];
        const float* f = (const float*)v;
        #pragma unroll
        for (int i = 0; i < 8; i++) {
            float s = f[i] * SCALE;
            h[i] = __float2half_rn(s);
            l[i] = __float2half_rn(s - __half2float(h[i]));
        }
        uint32_t rowAddr = sb + buf * 32768 + frow * 128;
        int x = frow & 7;
        uint32_t aH = rowAddr + ((foct ^ x) << 4);
        uint32_t aL = rowAddr + (((4 + foct) ^ x) << 4);
        uint4 ph = *(const uint4*)h;
        uint4 pl = *(const uint4*)l;
        asm volatile("st.shared.v4.b32 [%0], {%1,%2,%3,%4};" :: "r"(aH), "r"(ph.x), "r"(ph.y), "r"(ph.z), "r"(ph.w));
        asm volatile("st.shared.v4.b32 [%0], {%1,%2,%3,%4};" :: "r"(aL), "r"(pl.x), "r"(pl.y), "r"(pl.z), "r"(pl.w));
    };

    {
        issueB(0, 0); CP_COMMIT();
        float4 v[2];
        loadA(0, v);
        storeA(v, 0);
        CP_WAIT0();
        __syncthreads();
    }

    for (int ch = 0; ch < NCHUNK; ch++) {
        const int cur = ch & 1, nxt = cur ^ 1;
        float4 v[2];
        if (ch + 1 < NCHUNK) {
            loadA(ch + 1, v);
            issueB(ch + 1, nxt); CP_COMMIT();
        }

        #pragma unroll
        for (int kst = 0; kst < 2; kst++) {
            const int uH = 2 * kst, uL = 4 + 2 * kst;
            uint32_t aH[2][4], aL[2][4], bH[2][4], bL[2][4];
            LDSM4(aH[0], aAddr(cur, 0, uH)); LDSM4(aH[1], aAddr(cur, 1, uH));
            LDSM4(aL[0], aAddr(cur, 0, uL)); LDSM4(aL[1], aAddr(cur, 1, uL));
            LDSM4(bH[0], bAddr(cur, 0, uH)); LDSM4(bH[1], bAddr(cur, 1, uH));
            LDSM4(bL[0], bAddr(cur, 0, uL)); LDSM4(bL[1], bAddr(cur, 1, uL));
            #pragma unroll
            for (int mt = 0; mt < 2; mt++)
                #pragma unroll
                for (int ntp = 0; ntp < 2; ntp++) {
                    mma16(c[mt][ntp * 2],     aH[mt], bH[ntp]);
                    mma16(c[mt][ntp * 2 + 1], aH[mt], bH[ntp] + 2);
                    mma16(c[mt][ntp * 2],     aH[mt], bL[ntp]);
                    mma16(c[mt][ntp * 2 + 1], aH[mt], bL[ntp] + 2);
                    mma16(c[mt][ntp * 2],     aL[mt], bH[ntp]);
                    mma16(c[mt][ntp * 2 + 1], aL[mt], bH[ntp] + 2);
                }
        }

        if (ch + 1 < NCHUNK) {
            storeA(v, nxt);
            CP_WAIT0();
        }
        __syncthreads();
    }

    const int group = lane >> 2, tig = lane & 3;
    #pragma unroll
    for (int mt = 0; mt < 2; mt++) {
        int r0 = mBase + warpM * 32 + mt * 16 + group;
        #pragma unroll
        for (int nt = 0; nt < 4; nt++) {
            int n0 = nBase + warpN * 32 + nt * 8 + tig * 2;
            float be0 = (n0     < N_INNER) ? __ldg(beta + n0)     : 0.0f;
            float be1 = (n0 + 1 < N_INNER) ? __ldg(beta + n0 + 1) : 0.0f;
            float bi0 = (n0     < N_INNER) ? __ldg(bias + n0)     : 0.0f;
            float bi1 = (n0 + 1 < N_INNER) ? __ldg(bias + n0 + 1) : 0.0f;
            float2 o0, o1;
            {
                float z = be0 * (c[mt][nt][0] * SCALE_INV + bi0);
                o0.x = (n0 < N_INNER) ? 1.0f / (1.0f + expf(-z)) : 0.0f;
            }
            {
                float z = be1 * (c[mt][nt][1] * SCALE_INV + bi1);
                o0.y = (n0 + 1 < N_INNER) ? 1.0f / (1.0f + expf(-z)) : 0.0f;
            }
            {
                float z = be0 * (c[mt][nt][2] * SCALE_INV + bi0);
                o1.x = (n0 < N_INNER) ? 1.0f / (1.0f + expf(-z)) : 0.0f;
            }
            {
                float z = be1 * (c[mt][nt][3] * SCALE_INV + bi1);
                o1.y = (n0 + 1 < N_INNER) ? 1.0f / (1.0f + expf(-z)) : 0.0f;
            }
            *(float2*)(g_probs + (size_t)r0 * 256 + n0)       = o0;
            *(float2*)(g_probs + (size_t)(r0 + 8) * 256 + n0) = o1;
        }
    }
}

// ---------------- tree expansion + fused output gather ----------------
// one warp per row; lane owns leaves [lane*8, lane*8+8); writes out row inline.
__global__ __launch_bounds__(256)
void path_kernel(float* __restrict__ outRows) {
    __shared__ float sp[8][256];
    __shared__ float ls[256];
    __shared__ float red[256];
    const int warp = threadIdx.x >> 5, lane = threadIdx.x & 31;
    const int gw = blockIdx.x * 8 + warp;
    const int nw = gridDim.x * 8;
    const int base = lane * 8;

    ls[threadIdx.x] = 0.0f;
    __syncthreads();

    float lacc[8];
    #pragma unroll
    for (int k = 0; k < 8; k++) lacc[k] = 0.0f;
    float dacc = 0.0f;

    for (int b = gw; b < B_ROWS; b += nw) {
        const float* pr = g_probs + (size_t)b * 256;
        for (int i = lane; i < 256; i += 32) sp[warp][i] = pr[i];
        __syncwarp();

        float pre = 1.0f;
        #pragma unroll
        for (int d = 1; d <= 5; d++) {
            int g = (1 << (d - 1)) - 1 + (base >> (9 - d));
            int bit = (base >> (8 - d)) & 1;
            float pv = sp[warp][g];
            pre *= bit ? pv : (1.0f - pv);
        }
        float leaf[8];
        #pragma unroll
        for (int k = 0; k < 8; k++) {
            int l = base + k;
            float f = pre;
            #pragma unroll
            for (int d = 6; d <= 8; d++) {
                int g = (1 << (d - 1)) - 1 + (l >> (9 - d));
                int bit = (l >> (8 - d)) & 1;
                float pv = sp[warp][g];
                f *= bit ? pv : (1.0f - pv);
            }
            leaf[k] = f;
            lacc[k] += f;
        }

        int t = g_t[b];
        const float* lq = g_logQt + (size_t)t * 256 + base;
        float dl = 0.0f;
        #pragma unroll
        for (int k = 0; k < 8; k++) dl += leaf[k] * lq[k];
        dacc += dl;

        // argmax (first max wins)
        float bv = leaf[0]; int bi = base;
        #pragma unroll
        for (int k = 1; k < 8; k++) if (leaf[k] > bv) { bv = leaf[k]; bi = base + k; }
        for (int off = 16; off; off >>= 1) {
            float ov = __shfl_down_sync(0xffffffffu, bv, off);
            int   oi = __shfl_down_sync(0xffffffffu, bi, off);
            if (ov > bv || (ov == bv && oi < bi)) { bv = ov; bi = oi; }
        }
        bi = __shfl_sync(0xffffffffu, bi, 0);

        // fused gather: out[b,:] = Q[bi,:]  (Q is L2-resident)
        const float* q = g_Q + (size_t)bi * OUT_CL;
        float* o = outRows + (size_t)b * OUT_CL;
        #pragma unroll 4
        for (int j = lane; j < OUT_CL; j += 32) o[j] = __ldg(q + j);
        __syncwarp();
    }

    // block-level leaf-sum reduction (shared atomics), then 1 global atomic/leaf
    #pragma unroll
    for (int k = 0; k < 8; k++) atomicAdd(&ls[base + k], lacc[k]);
    __syncthreads();
    atomicAdd(&g_leafSum[threadIdx.x], ls[threadIdx.x]);

    red[threadIdx.x] = dacc;
    __syncthreads();
    for (int s = 128; s; s >>= 1) { if (threadIdx.x < s) red[threadIdx.x] += red[threadIdx.x + s]; __syncthreads(); }
    if (threadIdx.x == 0) atomicAdd(&g_lossSum, (double)red[0]);
}

// ---------------- finalize (parallel heap + alpha) ----------------
__global__ void final_kernel(float* __restrict__ out, int writeLoss) {
    __shared__ float H[255];
    __shared__ float Cs[128];
    const int tid = threadIdx.x;  // 128 threads

    if (tid < 128) H[127 + tid] = g_leafSum[2 * tid] + g_leafSum[2 * tid + 1];
    __syncthreads();
    for (int n = 64; n >= 1; n >>= 1) {
        int b0 = n - 1;
        if (tid < n) H[b0 + tid] = H[2 * (b0 + tid) + 1] + H[2 * (b0 + tid) + 2];
        __syncthreads();
    }

    float cpart = 0.0f;
    if (tid < 127) {
        int g = tid;
        int d = 32 - __clz(g + 1);          // depth 1..7
        float lm = 0.1f * exp2f((float)(-d)) * 0.5f;
        float denom = H[g];
        if (denom == 0.0f) denom = 1e-6f;
        float a = H[2 * g + 2] / denom;
        a = fminf(fmaxf(a, 1e-6f), 1.0f - 1e-6f);
        cpart = -lm * (logf(a) + log1pf(-a));
    }
    Cs[tid] = cpart;
    __syncthreads();
    for (int s = 64; s; s >>= 1) { if (tid < s) Cs[tid] += Cs[tid + s]; __syncthreads(); }
    if (tid == 0 && writeLoss) {
        double lt = g_lossSum / (double)B_ROWS;
        out[0] = (float)(-lt + (double)Cs[0]);
    }
}

extern "C" void kernel_launch(void* const* d_in, const int* in_sizes, int n_in,
                              void* d_out, int out_size) {
    const float* x    = (const float*)d_in[0];
    const float* y    = (const float*)d_in[1];
    const float* W    = (const float*)d_in[2];
    const float* bias = (const float*)d_in[3];
    const float* beta = (const float*)d_in[4];
    const float* lp   = (const float*)d_in[5];
    float* out = (float*)d_out;

    int hasLoss = (out_size >= B_ROWS * OUT_CL + 1) ? 1 : 0;
    float* outRows = out + hasLoss;

    static int smemSet = 0;
    if (!smemSet) {
        cudaFuncSetAttribute(gemm_mma_kernel, cudaFuncAttributeMaxDynamicSharedMemorySize, GEMM_SMEM);
        smemSet = 1;
    }

    init_kernel<<<1, 256>>>();
    wsplit_kernel<<<256, 256>>>(W);
    softmax_kernel<<<N_LEAF, 256>>>(lp);
    gemm_mma_kernel<<<dim3(2, 128), 512, GEMM_SMEM>>>(x, bias, beta);
    target_kernel<<<2048, 256>>>(y);
    path_kernel<<<256, 256>>>(outRows);
    final_kernel<<<1, 128>>>(out, hasLoss);
}